// round 14
// baseline (speedup 1.0000x reference)
#include <cuda_runtime.h>

// Fused MLP [N,2]->64->64->64->1, chaotic logistic-map activation.
// Round 14: output-split across warps. Block of 128 threads covers 128 points:
// thread t handles points (t&63, (t&63)+64) but only output half jh=t>>6.
// Warps are half-pure -> each warp reads only HALF the weights (still uniform
// broadcast): 16 weight LDS.128 per point-layer (2x better than best so far).
// Activations live in a single in-place smem stage, protected by two
// __syncthreads per layer; acc = 64 regs, no parking, no spills.

#define RCONST 3.82843f

typedef unsigned long long u64t;

struct SW {
    float W2t[4096];  // [k][j] transposed, stride 64
    float W3t[4096];
    float W1c0[64], W1c1[64];       // W1 column-split
    float b1[64], b2[64], b3[64], W4[64];
    float b4;
    float pad[3];
    // stage: hs[q*64 + p] = { packed h-pair (2q,2q+1) of point p, same of point p+64 }
    alignas(16) ulonglong2 hs[32 * 64];
};

__device__ __forceinline__ u64t pack2(float a, float b) {
    u64t r;
    asm("mov.b64 %0, {%1, %2};" : "=l"(r) : "f"(a), "f"(b));
    return r;
}

// act on a packed pair. iter1 exact rewrite: with x = 0.5*cos+0.5,
// R*x*(1-x) = fma(cos^2, -R/4, R/4). Then one more logistic step.
__device__ __forceinline__ u64t act2(u64t a, u64t NQR, u64t QR, u64t PR, u64t NR) {
    float lo, hi;
    asm("mov.b64 {%0, %1}, %2;" : "=f"(lo), "=f"(hi) : "l"(a));
    lo = __cosf(lo);
    hi = __cosf(hi);
    u64t c, c2, x1, u, v, r;
    asm("mov.b64 %0, {%1, %2};" : "=l"(c) : "f"(lo), "f"(hi));
    asm("mul.rn.f32x2 %0, %1, %1;" : "=l"(c2) : "l"(c));
    asm("fma.rn.f32x2 %0, %1, %2, %3;" : "=l"(x1) : "l"(c2), "l"(NQR), "l"(QR));
    asm("mul.rn.f32x2 %0, %1, %2;" : "=l"(u) : "l"(x1), "l"(PR));
    asm("mul.rn.f32x2 %0, %1, %2;" : "=l"(v) : "l"(x1), "l"(NR));
    asm("fma.rn.f32x2 %0, %1, %2, %3;" : "=l"(r) : "l"(v), "l"(x1), "l"(u));
    return r;
}

// One 64x64 layer: this thread computes 32 outputs (its j-half) for 2 points.
// Reads the whole stage; sync; writes its half's activations back in place; sync.
__device__ __forceinline__ void layer_half(SW* __restrict__ s, int p, int jh,
                                           const float* __restrict__ Wt,
                                           const float* __restrict__ b,
                                           u64t NQR, u64t QR, u64t PR, u64t NR) {
    u64t accA[16], accB[16];
    const u64t* bp = reinterpret_cast<const u64t*>(b);
#pragma unroll
    for (int i = 0; i < 16; ++i) {
        const u64t bb = bp[jh * 16 + i];
        accA[i] = bb;
        accB[i] = bb;
    }

#pragma unroll
    for (int q = 0; q < 32; ++q) {  // k-pair (2q, 2q+1)
        const ulonglong2 hq = s->hs[q * 64 + p];  // coalesced LDS.128
        float aLo, aHi, bLo, bHi;
        asm("mov.b64 {%0, %1}, %2;" : "=f"(aLo), "=f"(aHi) : "l"(hq.x));
        asm("mov.b64 {%0, %1}, %2;" : "=f"(bLo), "=f"(bHi) : "l"(hq.y));
        u64t hA0, hA1, hB0, hB1;
        asm("mov.b64 %0, {%1, %1};" : "=l"(hA0) : "f"(aLo));
        asm("mov.b64 %0, {%1, %1};" : "=l"(hA1) : "f"(aHi));
        asm("mov.b64 %0, {%1, %1};" : "=l"(hB0) : "f"(bLo));
        asm("mov.b64 %0, {%1, %1};" : "=l"(hB1) : "f"(bHi));
        // This warp's half-rows: 32 floats = 8 x LDS.128, warp-uniform broadcast.
        const ulonglong2* rA =
            reinterpret_cast<const ulonglong2*>(Wt + (2 * q) * 64 + jh * 32);
        const ulonglong2* rB =
            reinterpret_cast<const ulonglong2*>(Wt + (2 * q + 1) * 64 + jh * 32);
#pragma unroll
        for (int pp = 0; pp < 8; ++pp) {
            const ulonglong2 wa = rA[pp];  // j-pairs {2pp, 2pp+1}, k=2q
            asm("fma.rn.f32x2 %0, %1, %2, %0;" : "+l"(accA[2 * pp])     : "l"(hA0), "l"(wa.x));
            asm("fma.rn.f32x2 %0, %1, %2, %0;" : "+l"(accA[2 * pp + 1]) : "l"(hA0), "l"(wa.y));
            asm("fma.rn.f32x2 %0, %1, %2, %0;" : "+l"(accB[2 * pp])     : "l"(hB0), "l"(wa.x));
            asm("fma.rn.f32x2 %0, %1, %2, %0;" : "+l"(accB[2 * pp + 1]) : "l"(hB0), "l"(wa.y));
            const ulonglong2 wb = rB[pp];  // j-pairs {2pp, 2pp+1}, k=2q+1
            asm("fma.rn.f32x2 %0, %1, %2, %0;" : "+l"(accA[2 * pp])     : "l"(hA1), "l"(wb.x));
            asm("fma.rn.f32x2 %0, %1, %2, %0;" : "+l"(accA[2 * pp + 1]) : "l"(hA1), "l"(wb.y));
            asm("fma.rn.f32x2 %0, %1, %2, %0;" : "+l"(accB[2 * pp])     : "l"(hB1), "l"(wb.x));
            asm("fma.rn.f32x2 %0, %1, %2, %0;" : "+l"(accB[2 * pp + 1]) : "l"(hB1), "l"(wb.y));
        }
    }

    __syncthreads();  // everyone done READING the stage
#pragma unroll
    for (int i = 0; i < 16; ++i) {
        ulonglong2 v;
        v.x = act2(accA[i], NQR, QR, PR, NR);
        v.y = act2(accB[i], NQR, QR, PR, NR);
        s->hs[(jh * 16 + i) * 64 + p] = v;  // output j-pair = next layer's k-pair
    }
    __syncthreads();  // stage fully rewritten
}

extern __shared__ char smem_raw[];

__global__ void __launch_bounds__(128, 3) Model_17188459119206_kernel(
    const float* __restrict__ x,
    const float* __restrict__ gW1, const float* __restrict__ gb1,
    const float* __restrict__ gW2, const float* __restrict__ gb2,
    const float* __restrict__ gW3, const float* __restrict__ gb3,
    const float* __restrict__ gW4, const float* __restrict__ gb4,
    float* __restrict__ out, int n) {
    SW* s = reinterpret_cast<SW*>(smem_raw);
    const int t = threadIdx.x;
    const int p = t & 63;
    const int jh = t >> 6;

    // Stage weights (W2/W3 transposed to [k][j]).
#pragma unroll
    for (int m = t; m < 4096; m += 128) {
        const int j = m >> 6, k = m & 63;
        s->W2t[k * 64 + j] = gW2[m];
        s->W3t[k * 64 + j] = gW3[m];
    }
    if (t < 64) {
        s->W1c0[t] = gW1[2 * t];
        s->W1c1[t] = gW1[2 * t + 1];
        s->b1[t] = gb1[t];
        s->b2[t] = gb2[t];
        s->b3[t] = gb3[t];
        s->W4[t] = gW4[t];
    }
    if (t == 0) s->b4 = gb4[0];
    __syncthreads();

    const int base = blockIdx.x * 128;
    const int iA = base + p;
    const int iB = base + 64 + p;
    const int iAc = (iA < n) ? iA : 0;  // clamp loads; stores guarded at the end
    const int iBc = (iB < n) ? iB : 0;

    const u64t NQR = pack2(-0.25f * RCONST, -0.25f * RCONST);
    const u64t QR  = pack2(0.25f * RCONST, 0.25f * RCONST);
    const u64t PR  = pack2(RCONST, RCONST);
    const u64t NR  = pack2(-RCONST, -RCONST);

    const float2 pA = reinterpret_cast<const float2*>(x)[iAc];
    const float2 pB = reinterpret_cast<const float2*>(x)[iBc];
    u64t pxA, pyA, pxB, pyB;
    asm("mov.b64 %0, {%1, %1};" : "=l"(pxA) : "f"(pA.x));
    asm("mov.b64 %0, {%1, %1};" : "=l"(pyA) : "f"(pA.y));
    asm("mov.b64 %0, {%1, %1};" : "=l"(pxB) : "f"(pB.x));
    asm("mov.b64 %0, {%1, %1};" : "=l"(pyB) : "f"(pB.y));

    // Layer 1: 2 -> 64, this thread's j-half for both points, straight to stage.
    {
        const u64t* c0 = reinterpret_cast<const u64t*>(s->W1c0);
        const u64t* c1 = reinterpret_cast<const u64t*>(s->W1c1);
        const u64t* bp = reinterpret_cast<const u64t*>(s->b1);
#pragma unroll
        for (int i = 0; i < 16; ++i) {
            const int jq = jh * 16 + i;
            const u64t w0 = c0[jq], w1 = c1[jq], bb = bp[jq];
            u64t aA = bb, aB = bb;
            asm("fma.rn.f32x2 %0, %1, %2, %0;" : "+l"(aA) : "l"(pxA), "l"(w0));
            asm("fma.rn.f32x2 %0, %1, %2, %0;" : "+l"(aA) : "l"(pyA), "l"(w1));
            asm("fma.rn.f32x2 %0, %1, %2, %0;" : "+l"(aB) : "l"(pxB), "l"(w0));
            asm("fma.rn.f32x2 %0, %1, %2, %0;" : "+l"(aB) : "l"(pyB), "l"(w1));
            ulonglong2 v;
            v.x = act2(aA, NQR, QR, PR, NR);
            v.y = act2(aB, NQR, QR, PR, NR);
            s->hs[jq * 64 + p] = v;
        }
    }
    __syncthreads();

    // Layers 2,3: 64 -> 64, output-split across warp halves.
    layer_half(s, p, jh, s->W2t, s->b2, NQR, QR, PR, NR);
    layer_half(s, p, jh, s->W3t, s->b3, NQR, QR, PR, NR);

    // Layer 4: 64 -> 1. Threads 0..63 compute the full dot for their 2 points.
    if (t < 64) {
        u64t dA = pack2(0.0f, 0.0f), dB = pack2(0.0f, 0.0f);
        const u64t* w4 = reinterpret_cast<const u64t*>(s->W4);
#pragma unroll
        for (int q = 0; q < 32; ++q) {
            const ulonglong2 hq = s->hs[q * 64 + t];
            const u64t w = w4[q];
            asm("fma.rn.f32x2 %0, %1, %2, %0;" : "+l"(dA) : "l"(hq.x), "l"(w));
            asm("fma.rn.f32x2 %0, %1, %2, %0;" : "+l"(dB) : "l"(hq.y), "l"(w));
        }
        float aLo, aHi, bLo, bHi;
        asm("mov.b64 {%0, %1}, %2;" : "=f"(aLo), "=f"(aHi) : "l"(dA));
        asm("mov.b64 {%0, %1}, %2;" : "=f"(bLo), "=f"(bHi) : "l"(dB));
        const float sumA = aLo + aHi + s->b4;
        const float sumB = bLo + bHi + s->b4;

        if (iA < n) {
            const float c = __cosf(sumA);
            const float x1 = fmaf(c * c, -0.25f * RCONST, 0.25f * RCONST);
            out[iA] = fmaf(-RCONST * x1, x1, RCONST * x1);
        }
        if (iB < n) {
            const float c = __cosf(sumB);
            const float x1 = fmaf(c * c, -0.25f * RCONST, 0.25f * RCONST);
            out[iB] = fmaf(-RCONST * x1, x1, RCONST * x1);
        }
    }
}

extern "C" void kernel_launch(void* const* d_in, const int* in_sizes, int n_in,
                              void* d_out, int out_size) {
    const float* x = (const float*)d_in[0];
    const int n = in_sizes[0] / 2;  // x is [N, 2]

    cudaFuncSetAttribute(Model_17188459119206_kernel,
                         cudaFuncAttributeMaxDynamicSharedMemorySize,
                         (int)sizeof(SW));

    const int threads = 128;
    const int pts_per_block = 128;
    const int blocks = (n + pts_per_block - 1) / pts_per_block;
    Model_17188459119206_kernel<<<blocks, threads, sizeof(SW)>>>(
        x,
        (const float*)d_in[1], (const float*)d_in[2],
        (const float*)d_in[3], (const float*)d_in[4],
        (const float*)d_in[5], (const float*)d_in[6],
        (const float*)d_in[7], (const float*)d_in[8],
        (float*)d_out, n);
}